// round 1
// baseline (speedup 1.0000x reference)
#include <cuda_runtime.h>
#include <cstdint>
#include <math.h>

// Problem dims (fixed)
#define Bb 4
#define Ss 2048
#define Ee 512
#define Hh 1024
#define BS (Bb*Ss)       // 8192 token rows
#define BE (Bb*Ee)       // 2048 external rows
#define LS (Ee+1)        // 513 score columns (self + external)

// Scratch (device globals; allocation-free)
__device__ float g_q [BS*Hh];
__device__ float g_kt[BS*Hh];
__device__ float g_vt[BS*Hh];
__device__ float g_ke[BE*Hh];
__device__ float g_ve[BE*Hh];
__device__ float g_sc[(size_t)BS*LS];

// ---------------------------------------------------------------------------
// GEMM NN + bias: C[M,N] = A[M,K] @ W[K,N] + bias[N]
// 128x128 tile, BK=16, 256 threads, 8x8 microtile. M,N %128==0, K %16==0.
// ---------------------------------------------------------------------------
__global__ void __launch_bounds__(256, 2) gemm_nn_bias(
    const float* __restrict__ A, const float* __restrict__ W,
    const float* __restrict__ bias, float* __restrict__ C,
    int M, int N, int K)
{
    __shared__ float As[16][128];
    __shared__ float Bs[16][128];
    const int bm = blockIdx.y * 128;
    const int bn = blockIdx.x * 128;
    const int tid = threadIdx.x;
    const int tx = tid & 15;          // N microtile index
    const int ty = tid >> 4;          // M microtile index

    float acc[8][8];
    #pragma unroll
    for (int i = 0; i < 8; i++)
        #pragma unroll
        for (int j = 0; j < 8; j++) acc[i][j] = 0.f;

    const int ar = tid >> 2;              // 0..63  (A tile row)
    const int ac = (tid & 3) << 2;        // 0,4,8,12 (A tile k-offset)
    const int br = tid >> 5;              // 0..7   (B tile k-row)
    const int bc = (tid & 31) << 2;       // 0..124 (B tile n-offset)

    for (int k0 = 0; k0 < K; k0 += 16) {
        #pragma unroll
        for (int i = 0; i < 2; i++) {
            int r = ar + i * 64;
            float4 v = *(const float4*)(A + (size_t)(bm + r) * K + k0 + ac);
            As[ac + 0][r] = v.x; As[ac + 1][r] = v.y;
            As[ac + 2][r] = v.z; As[ac + 3][r] = v.w;
        }
        #pragma unroll
        for (int i = 0; i < 2; i++) {
            int r = br + i * 8;
            *(float4*)&Bs[r][bc] =
                *(const float4*)(W + (size_t)(k0 + r) * N + bn + bc);
        }
        __syncthreads();
        #pragma unroll
        for (int k = 0; k < 16; k++) {
            float ra[8], rb[8];
            *(float4*)&ra[0] = *(const float4*)&As[k][ty * 8];
            *(float4*)&ra[4] = *(const float4*)&As[k][ty * 8 + 4];
            *(float4*)&rb[0] = *(const float4*)&Bs[k][tx * 8];
            *(float4*)&rb[4] = *(const float4*)&Bs[k][tx * 8 + 4];
            #pragma unroll
            for (int i = 0; i < 8; i++)
                #pragma unroll
                for (int j = 0; j < 8; j++)
                    acc[i][j] = fmaf(ra[i], rb[j], acc[i][j]);
        }
        __syncthreads();
    }

    #pragma unroll
    for (int i = 0; i < 8; i++) {
        int row = bm + ty * 8 + i;
        #pragma unroll
        for (int j = 0; j < 8; j += 4) {
            int col = bn + tx * 8 + j;
            float4 o;
            o.x = acc[i][j + 0] + bias[col + 0];
            o.y = acc[i][j + 1] + bias[col + 1];
            o.z = acc[i][j + 2] + bias[col + 2];
            o.w = acc[i][j + 3] + bias[col + 3];
            *(float4*)(C + (size_t)row * N + col) = o;
        }
    }
}

// ---------------------------------------------------------------------------
// Batched NT GEMM: SC[b, s, 1+e] = Q[b,s,:] . KE[b,e,:]   (K = Hh)
// ---------------------------------------------------------------------------
__global__ void __launch_bounds__(256, 2) gemm_scores_nt(
    const float* __restrict__ Q, const float* __restrict__ KE,
    float* __restrict__ SC)
{
    const int b = blockIdx.z;
    const float* A  = Q  + (size_t)b * Ss * Hh;
    const float* Bm = KE + (size_t)b * Ee * Hh;

    __shared__ float As[16][128];
    __shared__ float Bs[16][128];
    const int bm = blockIdx.y * 128;
    const int bn = blockIdx.x * 128;
    const int tid = threadIdx.x;
    const int tx = tid & 15;
    const int ty = tid >> 4;

    float acc[8][8];
    #pragma unroll
    for (int i = 0; i < 8; i++)
        #pragma unroll
        for (int j = 0; j < 8; j++) acc[i][j] = 0.f;

    const int r4 = tid >> 2;
    const int c4 = (tid & 3) << 2;

    for (int k0 = 0; k0 < Hh; k0 += 16) {
        #pragma unroll
        for (int i = 0; i < 2; i++) {
            int r = r4 + i * 64;
            float4 v = *(const float4*)(A + (size_t)(bm + r) * Hh + k0 + c4);
            As[c4 + 0][r] = v.x; As[c4 + 1][r] = v.y;
            As[c4 + 2][r] = v.z; As[c4 + 3][r] = v.w;
        }
        #pragma unroll
        for (int i = 0; i < 2; i++) {
            int r = r4 + i * 64;
            float4 v = *(const float4*)(Bm + (size_t)(bn + r) * Hh + k0 + c4);
            Bs[c4 + 0][r] = v.x; Bs[c4 + 1][r] = v.y;
            Bs[c4 + 2][r] = v.z; Bs[c4 + 3][r] = v.w;
        }
        __syncthreads();
        #pragma unroll
        for (int k = 0; k < 16; k++) {
            float ra[8], rb[8];
            *(float4*)&ra[0] = *(const float4*)&As[k][ty * 8];
            *(float4*)&ra[4] = *(const float4*)&As[k][ty * 8 + 4];
            *(float4*)&rb[0] = *(const float4*)&Bs[k][tx * 8];
            *(float4*)&rb[4] = *(const float4*)&Bs[k][tx * 8 + 4];
            #pragma unroll
            for (int i = 0; i < 8; i++)
                #pragma unroll
                for (int j = 0; j < 8; j++)
                    acc[i][j] = fmaf(ra[i], rb[j], acc[i][j]);
        }
        __syncthreads();
    }

    #pragma unroll
    for (int i = 0; i < 8; i++) {
        size_t rowbase = (size_t)(b * Ss + bm + ty * 8 + i) * LS + 1 + bn;
        #pragma unroll
        for (int j = 0; j < 8; j++)
            SC[rowbase + tx * 8 + j] = acc[i][j];
    }
}

// ---------------------------------------------------------------------------
// Self-dot: SC[row, 0] = q[row,:] . k_tok[row,:]   (one warp per row)
// ---------------------------------------------------------------------------
__global__ void self_dot_kernel(const float* __restrict__ q,
                                const float* __restrict__ kt,
                                float* __restrict__ SC)
{
    int row  = blockIdx.x * 8 + (threadIdx.x >> 5);
    int lane = threadIdx.x & 31;
    const float4* q4 = (const float4*)(q  + (size_t)row * Hh);
    const float4* k4 = (const float4*)(kt + (size_t)row * Hh);
    float sum = 0.f;
    #pragma unroll
    for (int i = lane; i < Hh / 4; i += 32) {
        float4 a = q4[i], b = k4[i];
        sum += a.x * b.x + a.y * b.y + a.z * b.z + a.w * b.w;
    }
    #pragma unroll
    for (int o = 16; o; o >>= 1) sum += __shfl_xor_sync(0xffffffffu, sum, o);
    if (lane == 0) SC[(size_t)row * LS] = sum;
}

// ---------------------------------------------------------------------------
// Softmax over rows of length LS=513, in place. One block (128 thr) per row.
// ---------------------------------------------------------------------------
__global__ void softmax_kernel(float* __restrict__ SC)
{
    float* s = SC + (size_t)blockIdx.x * LS;
    const int tid = threadIdx.x;
    __shared__ float redm[4];
    __shared__ float reds[4];

    float v[5];
    float lmax = -INFINITY;
    #pragma unroll
    for (int i = 0; i < 5; i++) {
        int idx = tid + 128 * i;
        v[i] = (idx < LS) ? s[idx] : -INFINITY;
        lmax = fmaxf(lmax, v[i]);
    }
    #pragma unroll
    for (int o = 16; o; o >>= 1)
        lmax = fmaxf(lmax, __shfl_xor_sync(0xffffffffu, lmax, o));
    if ((tid & 31) == 0) redm[tid >> 5] = lmax;
    __syncthreads();
    float m = fmaxf(fmaxf(redm[0], redm[1]), fmaxf(redm[2], redm[3]));

    float lsum = 0.f;
    #pragma unroll
    for (int i = 0; i < 5; i++) {
        v[i] = expf(v[i] - m);   // exp(-inf)=0 handles the tail
        lsum += v[i];
    }
    #pragma unroll
    for (int o = 16; o; o >>= 1) lsum += __shfl_xor_sync(0xffffffffu, lsum, o);
    if ((tid & 31) == 0) reds[tid >> 5] = lsum;
    __syncthreads();
    float inv = 1.f / (reds[0] + reds[1] + reds[2] + reds[3]);

    #pragma unroll
    for (int i = 0; i < 5; i++) {
        int idx = tid + 128 * i;
        if (idx < LS) s[idx] = v[i] * inv;
    }
}

// ---------------------------------------------------------------------------
// Context: O[b,s,:] = p0 * v_tok[b,s,:] + P[b,s,1:] @ V_ext[b]   (K = Ee)
// ---------------------------------------------------------------------------
__global__ void __launch_bounds__(256, 2) gemm_ctx(
    const float* __restrict__ P, const float* __restrict__ VE,
    const float* __restrict__ VT, float* __restrict__ O)
{
    const int b = blockIdx.z;
    const float* Bbase = VE + (size_t)b * Ee * Hh;

    __shared__ float As[16][128];
    __shared__ float Bs[16][128];
    const int bm = blockIdx.y * 128;
    const int bn = blockIdx.x * 128;
    const int tid = threadIdx.x;
    const int tx = tid & 15;
    const int ty = tid >> 4;

    float acc[8][8];
    #pragma unroll
    for (int i = 0; i < 8; i++)
        #pragma unroll
        for (int j = 0; j < 8; j++) acc[i][j] = 0.f;

    const int ar = tid >> 2;
    const int ac = (tid & 3) << 2;
    const int br = tid >> 5;
    const int bc = (tid & 31) << 2;

    for (int k0 = 0; k0 < Ee; k0 += 16) {
        #pragma unroll
        for (int i = 0; i < 2; i++) {
            int r = ar + i * 64;
            const float* ap =
                P + (size_t)(b * Ss + bm + r) * LS + 1 + k0 + ac;
            As[ac + 0][r] = ap[0];
            As[ac + 1][r] = ap[1];
            As[ac + 2][r] = ap[2];
            As[ac + 3][r] = ap[3];
        }
        #pragma unroll
        for (int i = 0; i < 2; i++) {
            int r = br + i * 8;
            *(float4*)&Bs[r][bc] =
                *(const float4*)(Bbase + (size_t)(k0 + r) * Hh + bn + bc);
        }
        __syncthreads();
        #pragma unroll
        for (int k = 0; k < 16; k++) {
            float ra[8], rb[8];
            *(float4*)&ra[0] = *(const float4*)&As[k][ty * 8];
            *(float4*)&ra[4] = *(const float4*)&As[k][ty * 8 + 4];
            *(float4*)&rb[0] = *(const float4*)&Bs[k][tx * 8];
            *(float4*)&rb[4] = *(const float4*)&Bs[k][tx * 8 + 4];
            #pragma unroll
            for (int i = 0; i < 8; i++)
                #pragma unroll
                for (int j = 0; j < 8; j++)
                    acc[i][j] = fmaf(ra[i], rb[j], acc[i][j]);
        }
        __syncthreads();
    }

    #pragma unroll
    for (int i = 0; i < 8; i++) {
        int row = b * Ss + bm + ty * 8 + i;
        float p0 = P[(size_t)row * LS];
        #pragma unroll
        for (int j = 0; j < 8; j += 4) {
            int col = bn + tx * 8 + j;
            float4 vt = *(const float4*)(VT + (size_t)row * Hh + col);
            float4 o;
            o.x = fmaf(p0, vt.x, acc[i][j + 0]);
            o.y = fmaf(p0, vt.y, acc[i][j + 1]);
            o.z = fmaf(p0, vt.z, acc[i][j + 2]);
            o.w = fmaf(p0, vt.w, acc[i][j + 3]);
            *(float4*)(O + (size_t)row * Hh + col) = o;
        }
    }
}

// ---------------------------------------------------------------------------
extern "C" void kernel_launch(void* const* d_in, const int* in_sizes, int n_in,
                              void* d_out, int out_size)
{
    const float* hs  = (const float*)d_in[0];
    const float* ext = (const float*)d_in[1];
    const float* Wq  = (const float*)d_in[2];
    const float* bq  = (const float*)d_in[3];
    const float* Wk  = (const float*)d_in[4];
    const float* bk  = (const float*)d_in[5];
    const float* Wv  = (const float*)d_in[6];
    const float* bv  = (const float*)d_in[7];
    float* out = (float*)d_out;

    float *q, *kt, *vt, *ke, *ve, *sc;
    cudaGetSymbolAddress((void**)&q,  g_q);
    cudaGetSymbolAddress((void**)&kt, g_kt);
    cudaGetSymbolAddress((void**)&vt, g_vt);
    cudaGetSymbolAddress((void**)&ke, g_ke);
    cudaGetSymbolAddress((void**)&ve, g_ve);
    cudaGetSymbolAddress((void**)&sc, g_sc);

    dim3 blk(256);

    // Projections
    gemm_nn_bias<<<dim3(Hh / 128, BS / 128), blk>>>(hs,  Wq, bq, q,  BS, Hh, Hh);
    gemm_nn_bias<<<dim3(Hh / 128, BS / 128), blk>>>(hs,  Wk, bk, kt, BS, Hh, Hh);
    gemm_nn_bias<<<dim3(Hh / 128, BS / 128), blk>>>(hs,  Wv, bv, vt, BS, Hh, Hh);
    gemm_nn_bias<<<dim3(Hh / 128, BE / 128), blk>>>(ext, Wk, bk, ke, BE, Hh, Hh);
    gemm_nn_bias<<<dim3(Hh / 128, BE / 128), blk>>>(ext, Wv, bv, ve, BE, Hh, Hh);

    // Scores
    self_dot_kernel<<<BS / 8, 256>>>(q, kt, sc);
    gemm_scores_nt<<<dim3(Ee / 128, Ss / 128, Bb), blk>>>(q, ke, sc);

    // Softmax
    softmax_kernel<<<BS, 128>>>(sc);

    // Context
    gemm_ctx<<<dim3(Hh / 128, Ss / 128, Bb), blk>>>(sc, ve, vt, out);
}

// round 2
// speedup vs baseline: 1.0745x; 1.0745x over previous
#include <cuda_runtime.h>
#include <cstdint>
#include <math.h>

// Problem dims (fixed)
#define Bb 4
#define Ss 2048
#define Ee 512
#define Hh 1024
#define BS (Bb*Ss)       // 8192 token rows
#define BE (Bb*Ee)       // 2048 external rows
#define LS (Ee+1)        // 513 score columns (self + external)

typedef unsigned long long ull;

// Packed fp32x2 FMA (sm_103a): d = a*b + c per 32-bit lane of 64-bit regs.
#define FFMA2(d, a, b, c) \
    asm("fma.rn.f32x2 %0, %1, %2, %3;" : "=l"(d) : "l"(a), "l"(b), "l"(c))
// Duplicate one fp32 into both lanes of a 64-bit reg.
#define PACK2(d, x) \
    asm("mov.b64 %0, {%1, %1};" : "=l"(d) : "f"(x))

__device__ __forceinline__ float2 u2f2(ull v) {
    float2 r;
    asm("mov.b64 {%0, %1}, %2;" : "=f"(r.x), "=f"(r.y) : "l"(v));
    return r;
}

// Scratch (device globals; allocation-free)
__device__ float g_q [BS*Hh];
__device__ float g_kt[BS*Hh];
__device__ float g_vt[BS*Hh];
__device__ float g_ke[BE*Hh];
__device__ float g_ve[BE*Hh];
__device__ float g_sc[(size_t)BS*LS];

// One microtile row: broadcast a into both lanes, 4 FFMA2 against 8 B cols.
#define ROW_FMA(i, av)                                           \
    do { ull ad_; PACK2(ad_, av);                                \
        FFMA2(acc[i][0], ad_, b0.x, acc[i][0]);                  \
        FFMA2(acc[i][1], ad_, b0.y, acc[i][1]);                  \
        FFMA2(acc[i][2], ad_, b1.x, acc[i][2]);                  \
        FFMA2(acc[i][3], ad_, b1.y, acc[i][3]); } while (0)

// Compute one 16-k stage. ASTR/BSTR: row strides (floats) of the smem tiles.
#define COMPUTE_STAGE(ASbuf, BSbuf, ASTR, BSTR)                              \
    do {                                                                     \
        _Pragma("unroll")                                                    \
        for (int k = 0; k < 16; k++) {                                       \
            const float* arp_ = &(ASbuf)[k * (ASTR) + ty * 8];               \
            float4 a0 = *(const float4*)arp_;                                \
            float4 a1 = *(const float4*)(arp_ + 4);                          \
            ulonglong2 b0 = *(const ulonglong2*)&(BSbuf)[k * (BSTR) + tx*8]; \
            ulonglong2 b1 = *(const ulonglong2*)&(BSbuf)[k*(BSTR) + tx*8+4]; \
            ROW_FMA(0, a0.x); ROW_FMA(1, a0.y);                              \
            ROW_FMA(2, a0.z); ROW_FMA(3, a0.w);                              \
            ROW_FMA(4, a1.x); ROW_FMA(5, a1.y);                              \
            ROW_FMA(6, a1.z); ROW_FMA(7, a1.w);                              \
        }                                                                    \
    } while (0)

// ---------------------------------------------------------------------------
// GEMM NN + bias: C[M,N] = A[M,K] @ W[K,N] + bias[N]
// 128x128 tile, BK=16, 256 threads, 8x8 microtile (f32x2), double-buffered.
// ---------------------------------------------------------------------------
__global__ void __launch_bounds__(256, 2) gemm_nn_bias(
    const float* __restrict__ A, const float* __restrict__ W,
    const float* __restrict__ bias, float* __restrict__ C,
    int M, int N, int K)
{
    __shared__ float As[2][16 * 132];   // padded rows: conflict-free transpose
    __shared__ float Bs[2][16 * 128];
    const int bm = blockIdx.y * 128;
    const int bn = blockIdx.x * 128;
    const int tid = threadIdx.x;
    const int tx = tid & 15, ty = tid >> 4;
    const int ar = tid >> 2, ac = (tid & 3) << 2;
    const int br = tid >> 5, bc = (tid & 31) << 2;

    ull acc[8][4];
    #pragma unroll
    for (int i = 0; i < 8; i++)
        #pragma unroll
        for (int j = 0; j < 4; j++) acc[i][j] = 0ull;

    float4 pa0, pa1, pb0, pb1;

#define LOAD_PROJ(k0)                                                        \
    do {                                                                     \
        pa0 = *(const float4*)(A + (size_t)(bm + ar) * K + (k0) + ac);       \
        pa1 = *(const float4*)(A + (size_t)(bm + ar + 64) * K + (k0) + ac);  \
        pb0 = *(const float4*)(W + (size_t)((k0) + br) * N + bn + bc);       \
        pb1 = *(const float4*)(W + (size_t)((k0) + br + 8) * N + bn + bc);   \
    } while (0)
#define STS_PROJ(s)                                                          \
    do {                                                                     \
        As[s][(ac + 0) * 132 + ar] = pa0.x;                                  \
        As[s][(ac + 1) * 132 + ar] = pa0.y;                                  \
        As[s][(ac + 2) * 132 + ar] = pa0.z;                                  \
        As[s][(ac + 3) * 132 + ar] = pa0.w;                                  \
        As[s][(ac + 0) * 132 + ar + 64] = pa1.x;                             \
        As[s][(ac + 1) * 132 + ar + 64] = pa1.y;                             \
        As[s][(ac + 2) * 132 + ar + 64] = pa1.z;                             \
        As[s][(ac + 3) * 132 + ar + 64] = pa1.w;                             \
        *(float4*)&Bs[s][br * 128 + bc] = pb0;                               \
        *(float4*)&Bs[s][(br + 8) * 128 + bc] = pb1;                         \
    } while (0)

    LOAD_PROJ(0);
    STS_PROJ(0);
    __syncthreads();
    int buf = 0;
    for (int k0 = 0; k0 < K; k0 += 16) {
        const bool nxt = (k0 + 16 < K);
        if (nxt) LOAD_PROJ(k0 + 16);
        COMPUTE_STAGE(As[buf], Bs[buf], 132, 128);
        if (nxt) STS_PROJ(buf ^ 1);
        __syncthreads();
        buf ^= 1;
    }
#undef LOAD_PROJ
#undef STS_PROJ

    const float4 bi0 = *(const float4*)(bias + bn + tx * 8);
    const float4 bi1 = *(const float4*)(bias + bn + tx * 8 + 4);
    #pragma unroll
    for (int i = 0; i < 8; i++) {
        int row = bm + ty * 8 + i;
        float2 f0 = u2f2(acc[i][0]), f1 = u2f2(acc[i][1]);
        float2 f2 = u2f2(acc[i][2]), f3 = u2f2(acc[i][3]);
        float4 o0 = make_float4(f0.x + bi0.x, f0.y + bi0.y,
                                f1.x + bi0.z, f1.y + bi0.w);
        float4 o1 = make_float4(f2.x + bi1.x, f2.y + bi1.y,
                                f3.x + bi1.z, f3.y + bi1.w);
        *(float4*)(C + (size_t)row * N + bn + tx * 8) = o0;
        *(float4*)(C + (size_t)row * N + bn + tx * 8 + 4) = o1;
    }
}

// ---------------------------------------------------------------------------
// Batched NT GEMM: SC[b, s, 1+e] = Q[b,s,:] . KE[b,e,:]   (K = Hh)
// Both operands K-major: transpose both into padded smem.
// ---------------------------------------------------------------------------
__global__ void __launch_bounds__(256, 2) gemm_scores_nt(
    const float* __restrict__ Q, const float* __restrict__ KE,
    float* __restrict__ SC)
{
    const int b = blockIdx.z;
    const float* Aq = Q  + (size_t)b * Ss * Hh;
    const float* Bk = KE + (size_t)b * Ee * Hh;

    __shared__ float As[2][16 * 132];
    __shared__ float Bs[2][16 * 132];
    const int bm = blockIdx.y * 128;
    const int bn = blockIdx.x * 128;
    const int tid = threadIdx.x;
    const int tx = tid & 15, ty = tid >> 4;
    const int ar = tid >> 2, ac = (tid & 3) << 2;

    ull acc[8][4];
    #pragma unroll
    for (int i = 0; i < 8; i++)
        #pragma unroll
        for (int j = 0; j < 4; j++) acc[i][j] = 0ull;

    float4 pa0, pa1, pb0, pb1;

#define LOAD_SCR(k0)                                                         \
    do {                                                                     \
        pa0 = *(const float4*)(Aq + (size_t)(bm + ar) * Hh + (k0) + ac);     \
        pa1 = *(const float4*)(Aq + (size_t)(bm + ar + 64) * Hh + (k0) + ac);\
        pb0 = *(const float4*)(Bk + (size_t)(bn + ar) * Hh + (k0) + ac);     \
        pb1 = *(const float4*)(Bk + (size_t)(bn + ar + 64) * Hh + (k0) + ac);\
    } while (0)
#define STS_SCR(s)                                                           \
    do {                                                                     \
        As[s][(ac + 0) * 132 + ar] = pa0.x;                                  \
        As[s][(ac + 1) * 132 + ar] = pa0.y;                                  \
        As[s][(ac + 2) * 132 + ar] = pa0.z;                                  \
        As[s][(ac + 3) * 132 + ar] = pa0.w;                                  \
        As[s][(ac + 0) * 132 + ar + 64] = pa1.x;                             \
        As[s][(ac + 1) * 132 + ar + 64] = pa1.y;                             \
        As[s][(ac + 2) * 132 + ar + 64] = pa1.z;                             \
        As[s][(ac + 3) * 132 + ar + 64] = pa1.w;                             \
        Bs[s][(ac + 0) * 132 + ar] = pb0.x;                                  \
        Bs[s][(ac + 1) * 132 + ar] = pb0.y;                                  \
        Bs[s][(ac + 2) * 132 + ar] = pb0.z;                                  \
        Bs[s][(ac + 3) * 132 + ar] = pb0.w;                                  \
        Bs[s][(ac + 0) * 132 + ar + 64] = pb1.x;                             \
        Bs[s][(ac + 1) * 132 + ar + 64] = pb1.y;                             \
        Bs[s][(ac + 2) * 132 + ar + 64] = pb1.z;                             \
        Bs[s][(ac + 3) * 132 + ar + 64] = pb1.w;                             \
    } while (0)

    LOAD_SCR(0);
    STS_SCR(0);
    __syncthreads();
    int buf = 0;
    for (int k0 = 0; k0 < Hh; k0 += 16) {
        const bool nxt = (k0 + 16 < Hh);
        if (nxt) LOAD_SCR(k0 + 16);
        COMPUTE_STAGE(As[buf], Bs[buf], 132, 132);
        if (nxt) STS_SCR(buf ^ 1);
        __syncthreads();
        buf ^= 1;
    }
#undef LOAD_SCR
#undef STS_SCR

    #pragma unroll
    for (int i = 0; i < 8; i++) {
        size_t rowbase = (size_t)(b * Ss + bm + ty * 8 + i) * LS + 1 + bn;
        #pragma unroll
        for (int jp = 0; jp < 4; jp++) {
            float2 f = u2f2(acc[i][jp]);
            SC[rowbase + tx * 8 + jp * 2 + 0] = f.x;
            SC[rowbase + tx * 8 + jp * 2 + 1] = f.y;
        }
    }
}

// ---------------------------------------------------------------------------
// Self-dot: SC[row, 0] = q[row,:] . k_tok[row,:]   (one warp per row)
// ---------------------------------------------------------------------------
__global__ void self_dot_kernel(const float* __restrict__ q,
                                const float* __restrict__ kt,
                                float* __restrict__ SC)
{
    int row  = blockIdx.x * 8 + (threadIdx.x >> 5);
    int lane = threadIdx.x & 31;
    const float4* q4 = (const float4*)(q  + (size_t)row * Hh);
    const float4* k4 = (const float4*)(kt + (size_t)row * Hh);
    float sum = 0.f;
    #pragma unroll
    for (int i = lane; i < Hh / 4; i += 32) {
        float4 a = q4[i], b = k4[i];
        sum += a.x * b.x + a.y * b.y + a.z * b.z + a.w * b.w;
    }
    #pragma unroll
    for (int o = 16; o; o >>= 1) sum += __shfl_xor_sync(0xffffffffu, sum, o);
    if (lane == 0) SC[(size_t)row * LS] = sum;
}

// ---------------------------------------------------------------------------
// Softmax over rows of length LS=513, in place. One block (128 thr) per row.
// ---------------------------------------------------------------------------
__global__ void softmax_kernel(float* __restrict__ SC)
{
    float* s = SC + (size_t)blockIdx.x * LS;
    const int tid = threadIdx.x;
    __shared__ float redm[4];
    __shared__ float reds[4];

    float v[5];
    float lmax = -INFINITY;
    #pragma unroll
    for (int i = 0; i < 5; i++) {
        int idx = tid + 128 * i;
        v[i] = (idx < LS) ? s[idx] : -INFINITY;
        lmax = fmaxf(lmax, v[i]);
    }
    #pragma unroll
    for (int o = 16; o; o >>= 1)
        lmax = fmaxf(lmax, __shfl_xor_sync(0xffffffffu, lmax, o));
    if ((tid & 31) == 0) redm[tid >> 5] = lmax;
    __syncthreads();
    float m = fmaxf(fmaxf(redm[0], redm[1]), fmaxf(redm[2], redm[3]));

    float lsum = 0.f;
    #pragma unroll
    for (int i = 0; i < 5; i++) {
        v[i] = expf(v[i] - m);
        lsum += v[i];
    }
    #pragma unroll
    for (int o = 16; o; o >>= 1) lsum += __shfl_xor_sync(0xffffffffu, lsum, o);
    if ((tid & 31) == 0) reds[tid >> 5] = lsum;
    __syncthreads();
    float inv = 1.f / (reds[0] + reds[1] + reds[2] + reds[3]);

    #pragma unroll
    for (int i = 0; i < 5; i++) {
        int idx = tid + 128 * i;
        if (idx < LS) s[idx] = v[i] * inv;
    }
}

// ---------------------------------------------------------------------------
// Context: O[b,s,:] = p0 * v_tok[b,s,:] + P[b,s,1:] @ V_ext[b]   (K = Ee)
// ---------------------------------------------------------------------------
__global__ void __launch_bounds__(256, 2) gemm_ctx(
    const float* __restrict__ P, const float* __restrict__ VE,
    const float* __restrict__ VT, float* __restrict__ O)
{
    const int b = blockIdx.z;
    const float* Bbase = VE + (size_t)b * Ee * Hh;

    __shared__ float As[2][16 * 132];
    __shared__ float Bs[2][16 * 128];
    const int bm = blockIdx.y * 128;
    const int bn = blockIdx.x * 128;
    const int tid = threadIdx.x;
    const int tx = tid & 15, ty = tid >> 4;
    const int ar = tid >> 2, ac = (tid & 3) << 2;
    const int br = tid >> 5, bc = (tid & 31) << 2;

    ull acc[8][4];
    #pragma unroll
    for (int i = 0; i < 8; i++)
        #pragma unroll
        for (int j = 0; j < 4; j++) acc[i][j] = 0ull;

    float pav[2][4];
    float4 pb0, pb1;

#define LOAD_CTX(k0)                                                         \
    do {                                                                     \
        const float* ap0 = P + (size_t)(b * Ss + bm + ar) * LS + 1 + (k0) + ac;      \
        const float* ap1 = P + (size_t)(b * Ss + bm + ar + 64) * LS + 1 + (k0) + ac; \
        pav[0][0] = ap0[0]; pav[0][1] = ap0[1];                              \
        pav[0][2] = ap0[2]; pav[0][3] = ap0[3];                              \
        pav[1][0] = ap1[0]; pav[1][1] = ap1[1];                              \
        pav[1][2] = ap1[2]; pav[1][3] = ap1[3];                              \
        pb0 = *(const float4*)(Bbase + (size_t)((k0) + br) * Hh + bn + bc);  \
        pb1 = *(const float4*)(Bbase + (size_t)((k0) + br + 8) * Hh + bn + bc); \
    } while (0)
#define STS_CTX(s)                                                           \
    do {                                                                     \
        As[s][(ac + 0) * 132 + ar] = pav[0][0];                              \
        As[s][(ac + 1) * 132 + ar] = pav[0][1];                              \
        As[s][(ac + 2) * 132 + ar] = pav[0][2];                              \
        As[s][(ac + 3) * 132 + ar] = pav[0][3];                              \
        As[s][(ac + 0) * 132 + ar + 64] = pav[1][0];                         \
        As[s][(ac + 1) * 132 + ar + 64] = pav[1][1];                         \
        As[s][(ac + 2) * 132 + ar + 64] = pav[1][2];                         \
        As[s][(ac + 3) * 132 + ar + 64] = pav[1][3];                         \
        *(float4*)&Bs[s][br * 128 + bc] = pb0;                               \
        *(float4*)&Bs[s][(br + 8) * 128 + bc] = pb1;                         \
    } while (0)

    LOAD_CTX(0);
    STS_CTX(0);
    __syncthreads();
    int buf = 0;
    for (int k0 = 0; k0 < Ee; k0 += 16) {
        const bool nxt = (k0 + 16 < Ee);
        if (nxt) LOAD_CTX(k0 + 16);
        COMPUTE_STAGE(As[buf], Bs[buf], 132, 128);
        if (nxt) STS_CTX(buf ^ 1);
        __syncthreads();
        buf ^= 1;
    }
#undef LOAD_CTX
#undef STS_CTX

    #pragma unroll
    for (int i = 0; i < 8; i++) {
        int row = b * Ss + bm + ty * 8 + i;
        float p0 = P[(size_t)row * LS];
        float2 f0 = u2f2(acc[i][0]), f1 = u2f2(acc[i][1]);
        float2 f2 = u2f2(acc[i][2]), f3 = u2f2(acc[i][3]);
        int col = bn + tx * 8;
        float4 vt0 = *(const float4*)(VT + (size_t)row * Hh + col);
        float4 vt1 = *(const float4*)(VT + (size_t)row * Hh + col + 4);
        float4 o0 = make_float4(fmaf(p0, vt0.x, f0.x), fmaf(p0, vt0.y, f0.y),
                                fmaf(p0, vt0.z, f1.x), fmaf(p0, vt0.w, f1.y));
        float4 o1 = make_float4(fmaf(p0, vt1.x, f2.x), fmaf(p0, vt1.y, f2.y),
                                fmaf(p0, vt1.z, f3.x), fmaf(p0, vt1.w, f3.y));
        *(float4*)(O + (size_t)row * Hh + col) = o0;
        *(float4*)(O + (size_t)row * Hh + col + 4) = o1;
    }
}

// ---------------------------------------------------------------------------
extern "C" void kernel_launch(void* const* d_in, const int* in_sizes, int n_in,
                              void* d_out, int out_size)
{
    const float* hs  = (const float*)d_in[0];
    const float* ext = (const float*)d_in[1];
    const float* Wq  = (const float*)d_in[2];
    const float* bq  = (const float*)d_in[3];
    const float* Wk  = (const float*)d_in[4];
    const float* bk  = (const float*)d_in[5];
    const float* Wv  = (const float*)d_in[6];
    const float* bv  = (const float*)d_in[7];
    float* out = (float*)d_out;

    float *q, *kt, *vt, *ke, *ve, *sc;
    cudaGetSymbolAddress((void**)&q,  g_q);
    cudaGetSymbolAddress((void**)&kt, g_kt);
    cudaGetSymbolAddress((void**)&vt, g_vt);
    cudaGetSymbolAddress((void**)&ke, g_ke);
    cudaGetSymbolAddress((void**)&ve, g_ve);
    cudaGetSymbolAddress((void**)&sc, g_sc);

    dim3 blk(256);

    // Projections
    gemm_nn_bias<<<dim3(Hh / 128, BS / 128), blk>>>(hs,  Wq, bq, q,  BS, Hh, Hh);
    gemm_nn_bias<<<dim3(Hh / 128, BS / 128), blk>>>(hs,  Wk, bk, kt, BS, Hh, Hh);
    gemm_nn_bias<<<dim3(Hh / 128, BS / 128), blk>>>(hs,  Wv, bv, vt, BS, Hh, Hh);
    gemm_nn_bias<<<dim3(Hh / 128, BE / 128), blk>>>(ext, Wk, bk, ke, BE, Hh, Hh);
    gemm_nn_bias<<<dim3(Hh / 128, BE / 128), blk>>>(ext, Wv, bv, ve, BE, Hh, Hh);

    // Scores
    self_dot_kernel<<<BS / 8, 256>>>(q, kt, sc);
    gemm_scores_nt<<<dim3(Ee / 128, Ss / 128, Bb), blk>>>(q, ke, sc);

    // Softmax
    softmax_kernel<<<BS, 128>>>(sc);

    // Context
    gemm_ctx<<<dim3(Hh / 128, Ss / 128, Bb), blk>>>(sc, ve, vt, out);
}

// round 3
// speedup vs baseline: 1.5487x; 1.4413x over previous
#include <cuda_runtime.h>
#include <cstdint>
#include <math.h>

// Problem dims (fixed)
#define Bb 4
#define Ss 2048
#define Ee 512
#define Hh 1024
#define BS (Bb*Ss)       // 8192 token rows
#define BE (Bb*Ee)       // 2048 external rows
#define LS (Ee+1)        // 513 score columns

// Scratch (device globals; allocation-free)
__device__ float g_q [BS*Hh];
__device__ float g_kt[BS*Hh];
__device__ float g_vt[BS*Hh];
__device__ float g_ke[BE*Hh];
__device__ float g_ve[BE*Hh];
__device__ float g_sc[(size_t)BS*LS];

#define HIMASK 0xFFFFE000u
#define SSTR 136   // smem row stride (floats): conflict-free frag LDS

// Split fp32 x into tf32 hi/lo: x ~= hi + lo, |missing| ~ 1e-6 |x|
__device__ __forceinline__ void split_tf32(float x, uint32_t &h, uint32_t &l)
{
    uint32_t hb = __float_as_uint(x) & HIMASK;
    h = hb;
    float r = x - __uint_as_float(hb);
    l = __float_as_uint(r) & HIMASK;
}

__device__ __forceinline__ void mma8(float* d, const uint32_t* a, const uint32_t* b)
{
    asm volatile(
        "mma.sync.aligned.m16n8k8.row.col.f32.tf32.tf32.f32 "
        "{%0,%1,%2,%3}, {%4,%5,%6,%7}, {%8,%9}, {%0,%1,%2,%3};"
        : "+f"(d[0]), "+f"(d[1]), "+f"(d[2]), "+f"(d[3])
        : "r"(a[0]), "r"(a[1]), "r"(a[2]), "r"(a[3]),
          "r"(b[0]), "r"(b[1]));
}

// Compute both k8 sub-steps of one BK=16 stage from smem (As/Bs: [k][mn], SSTR).
// Needs in scope: wm, wn, gid, tg, float acc[4][4][4].
#define FRAG_COMPUTE(Abuf, Bbuf)                                              \
  do {                                                                        \
    _Pragma("unroll")                                                         \
    for (int kk = 0; kk < 16; kk += 8) {                                      \
      uint32_t ah[4][4], al[4][4], bh[4][2], bl[4][2];                        \
      _Pragma("unroll")                                                       \
      for (int mt = 0; mt < 4; mt++) {                                        \
        int mbase = wm * 64 + mt * 16 + gid;                                  \
        _Pragma("unroll")                                                     \
        for (int h = 0; h < 2; h++) {                                         \
          float v0 = (Abuf)[(kk + tg + h * 4) * SSTR + mbase];                \
          float v1 = (Abuf)[(kk + tg + h * 4) * SSTR + mbase + 8];            \
          split_tf32(v0, ah[mt][h * 2 + 0], al[mt][h * 2 + 0]);               \
          split_tf32(v1, ah[mt][h * 2 + 1], al[mt][h * 2 + 1]);               \
        }                                                                     \
      }                                                                       \
      _Pragma("unroll")                                                       \
      for (int nt = 0; nt < 4; nt++) {                                        \
        int nbase = wn * 32 + nt * 8 + gid;                                   \
        float w0 = (Bbuf)[(kk + tg) * SSTR + nbase];                          \
        float w1 = (Bbuf)[(kk + tg + 4) * SSTR + nbase];                      \
        split_tf32(w0, bh[nt][0], bl[nt][0]);                                 \
        split_tf32(w1, bh[nt][1], bl[nt][1]);                                 \
      }                                                                       \
      _Pragma("unroll")                                                       \
      for (int mt = 0; mt < 4; mt++)                                          \
        _Pragma("unroll")                                                     \
        for (int nt = 0; nt < 4; nt++) {                                      \
          mma8(acc[mt][nt], ah[mt], bh[nt]);                                  \
          mma8(acc[mt][nt], ah[mt], bl[nt]);                                  \
          mma8(acc[mt][nt], al[mt], bh[nt]);                                  \
        }                                                                     \
    }                                                                         \
  } while (0)

#define ACC_INIT                                                              \
    float acc[4][4][4];                                                      \
    _Pragma("unroll")                                                         \
    for (int i = 0; i < 4; i++)                                               \
      _Pragma("unroll")                                                       \
      for (int j = 0; j < 4; j++)                                             \
        _Pragma("unroll")                                                     \
        for (int t = 0; t < 4; t++) acc[i][j][t] = 0.f;

#define WARP_IDS                                                              \
    const int tid = threadIdx.x;                                              \
    const int warp = tid >> 5, lane = tid & 31;                               \
    const int wm = warp & 1, wn = warp >> 1;                                  \
    const int gid = lane >> 2, tg = lane & 3;

// ---------------------------------------------------------------------------
// GEMM NN + bias: C[M,N] = A[M,K] @ W[K,N] + bias[N].  128x128 tile, BK=16.
// ---------------------------------------------------------------------------
__global__ void __launch_bounds__(256) gemm_nn_bias(
    const float* __restrict__ A, const float* __restrict__ W,
    const float* __restrict__ bias, float* __restrict__ C,
    int M, int N, int K)
{
    __shared__ float As[2][16 * SSTR];
    __shared__ float Bs[2][16 * SSTR];
    const int bm = blockIdx.y * 128;
    const int bn = blockIdx.x * 128;
    WARP_IDS;
    const int ar = tid >> 2, ac = (tid & 3) << 2;
    const int br = tid >> 5, bc = (tid & 31) << 2;

    ACC_INIT;
    float4 pa0, pa1, pb0, pb1;

#define LOAD_P(k0)                                                            \
    do {                                                                      \
        pa0 = *(const float4*)(A + (size_t)(bm + ar) * K + (k0) + ac);        \
        pa1 = *(const float4*)(A + (size_t)(bm + ar + 64) * K + (k0) + ac);   \
        pb0 = *(const float4*)(W + (size_t)((k0) + br) * N + bn + bc);        \
        pb1 = *(const float4*)(W + (size_t)((k0) + br + 8) * N + bn + bc);    \
    } while (0)
#define STS_P(s)                                                              \
    do {                                                                      \
        As[s][(ac + 0) * SSTR + ar] = pa0.x;                                  \
        As[s][(ac + 1) * SSTR + ar] = pa0.y;                                  \
        As[s][(ac + 2) * SSTR + ar] = pa0.z;                                  \
        As[s][(ac + 3) * SSTR + ar] = pa0.w;                                  \
        As[s][(ac + 0) * SSTR + ar + 64] = pa1.x;                             \
        As[s][(ac + 1) * SSTR + ar + 64] = pa1.y;                             \
        As[s][(ac + 2) * SSTR + ar + 64] = pa1.z;                             \
        As[s][(ac + 3) * SSTR + ar + 64] = pa1.w;                             \
        *(float4*)&Bs[s][br * SSTR + bc] = pb0;                               \
        *(float4*)&Bs[s][(br + 8) * SSTR + bc] = pb1;                         \
    } while (0)

    LOAD_P(0);
    STS_P(0);
    __syncthreads();
    int buf = 0;
    for (int k0 = 0; k0 < K; k0 += 16) {
        const bool nxt = (k0 + 16 < K);
        if (nxt) LOAD_P(k0 + 16);
        FRAG_COMPUTE(As[buf], Bs[buf]);
        if (nxt) STS_P(buf ^ 1);
        __syncthreads();
        buf ^= 1;
    }
#undef LOAD_P
#undef STS_P

    #pragma unroll
    for (int mt = 0; mt < 4; mt++) {
        int r0 = bm + wm * 64 + mt * 16 + gid;
        #pragma unroll
        for (int nt = 0; nt < 4; nt++) {
            int col = bn + wn * 32 + nt * 8 + 2 * tg;
            float2 bi = *(const float2*)(bias + col);
            float2 o0 = make_float2(acc[mt][nt][0] + bi.x,
                                    acc[mt][nt][1] + bi.y);
            float2 o1 = make_float2(acc[mt][nt][2] + bi.x,
                                    acc[mt][nt][3] + bi.y);
            *(float2*)(C + (size_t)r0 * N + col) = o0;
            *(float2*)(C + (size_t)(r0 + 8) * N + col) = o1;
        }
    }
}

// ---------------------------------------------------------------------------
// Batched NT GEMM: SC[b, s, 1+e] = Q[b,s,:] . KE[b,e,:]  (K = Hh)
// ---------------------------------------------------------------------------
__global__ void __launch_bounds__(256) gemm_scores_nt(
    const float* __restrict__ Q, const float* __restrict__ KE,
    float* __restrict__ SC)
{
    const int b = blockIdx.z;
    const float* Aq = Q  + (size_t)b * Ss * Hh;
    const float* Bk = KE + (size_t)b * Ee * Hh;

    __shared__ float As[2][16 * SSTR];
    __shared__ float Bs[2][16 * SSTR];
    const int bm = blockIdx.y * 128;
    const int bn = blockIdx.x * 128;
    WARP_IDS;
    const int ar = tid >> 2, ac = (tid & 3) << 2;

    ACC_INIT;
    float4 pa0, pa1, pb0, pb1;

#define LOAD_S(k0)                                                            \
    do {                                                                      \
        pa0 = *(const float4*)(Aq + (size_t)(bm + ar) * Hh + (k0) + ac);      \
        pa1 = *(const float4*)(Aq + (size_t)(bm + ar + 64) * Hh + (k0) + ac); \
        pb0 = *(const float4*)(Bk + (size_t)(bn + ar) * Hh + (k0) + ac);      \
        pb1 = *(const float4*)(Bk + (size_t)(bn + ar + 64) * Hh + (k0) + ac); \
    } while (0)
#define STS_S(s)                                                              \
    do {                                                                      \
        As[s][(ac + 0) * SSTR + ar] = pa0.x;                                  \
        As[s][(ac + 1) * SSTR + ar] = pa0.y;                                  \
        As[s][(ac + 2) * SSTR + ar] = pa0.z;                                  \
        As[s][(ac + 3) * SSTR + ar] = pa0.w;                                  \
        As[s][(ac + 0) * SSTR + ar + 64] = pa1.x;                             \
        As[s][(ac + 1) * SSTR + ar + 64] = pa1.y;                             \
        As[s][(ac + 2) * SSTR + ar + 64] = pa1.z;                             \
        As[s][(ac + 3) * SSTR + ar + 64] = pa1.w;                             \
        Bs[s][(ac + 0) * SSTR + ar] = pb0.x;                                  \
        Bs[s][(ac + 1) * SSTR + ar] = pb0.y;                                  \
        Bs[s][(ac + 2) * SSTR + ar] = pb0.z;                                  \
        Bs[s][(ac + 3) * SSTR + ar] = pb0.w;                                  \
        Bs[s][(ac + 0) * SSTR + ar + 64] = pb1.x;                             \
        Bs[s][(ac + 1) * SSTR + ar + 64] = pb1.y;                             \
        Bs[s][(ac + 2) * SSTR + ar + 64] = pb1.z;                             \
        Bs[s][(ac + 3) * SSTR + ar + 64] = pb1.w;                             \
    } while (0)

    LOAD_S(0);
    STS_S(0);
    __syncthreads();
    int buf = 0;
    for (int k0 = 0; k0 < Hh; k0 += 16) {
        const bool nxt = (k0 + 16 < Hh);
        if (nxt) LOAD_S(k0 + 16);
        FRAG_COMPUTE(As[buf], Bs[buf]);
        if (nxt) STS_S(buf ^ 1);
        __syncthreads();
        buf ^= 1;
    }
#undef LOAD_S
#undef STS_S

    #pragma unroll
    for (int mt = 0; mt < 4; mt++) {
        int row = b * Ss + bm + wm * 64 + mt * 16 + gid;
        #pragma unroll
        for (int nt = 0; nt < 4; nt++) {
            int col = bn + wn * 32 + nt * 8 + 2 * tg;
            size_t base0 = (size_t)row * LS + 1 + col;
            size_t base1 = (size_t)(row + 8) * LS + 1 + col;
            SC[base0]     = acc[mt][nt][0];
            SC[base0 + 1] = acc[mt][nt][1];
            SC[base1]     = acc[mt][nt][2];
            SC[base1 + 1] = acc[mt][nt][3];
        }
    }
}

// ---------------------------------------------------------------------------
// Self-dot: SC[row, 0] = q[row,:] . k_tok[row,:]   (fp32, one warp per row)
// ---------------------------------------------------------------------------
__global__ void self_dot_kernel(const float* __restrict__ q,
                                const float* __restrict__ kt,
                                float* __restrict__ SC)
{
    int row  = blockIdx.x * 8 + (threadIdx.x >> 5);
    int lane = threadIdx.x & 31;
    const float4* q4 = (const float4*)(q  + (size_t)row * Hh);
    const float4* k4 = (const float4*)(kt + (size_t)row * Hh);
    float sum = 0.f;
    #pragma unroll
    for (int i = lane; i < Hh / 4; i += 32) {
        float4 a = q4[i], b = k4[i];
        sum += a.x * b.x + a.y * b.y + a.z * b.z + a.w * b.w;
    }
    #pragma unroll
    for (int o = 16; o; o >>= 1) sum += __shfl_xor_sync(0xffffffffu, sum, o);
    if (lane == 0) SC[(size_t)row * LS] = sum;
}

// ---------------------------------------------------------------------------
// Softmax over rows of length LS=513, in place. One block (128 thr) per row.
// ---------------------------------------------------------------------------
__global__ void softmax_kernel(float* __restrict__ SC)
{
    float* s = SC + (size_t)blockIdx.x * LS;
    const int tid = threadIdx.x;
    __shared__ float redm[4];
    __shared__ float reds[4];

    float v[5];
    float lmax = -INFINITY;
    #pragma unroll
    for (int i = 0; i < 5; i++) {
        int idx = tid + 128 * i;
        v[i] = (idx < LS) ? s[idx] : -INFINITY;
        lmax = fmaxf(lmax, v[i]);
    }
    #pragma unroll
    for (int o = 16; o; o >>= 1)
        lmax = fmaxf(lmax, __shfl_xor_sync(0xffffffffu, lmax, o));
    if ((tid & 31) == 0) redm[tid >> 5] = lmax;
    __syncthreads();
    float m = fmaxf(fmaxf(redm[0], redm[1]), fmaxf(redm[2], redm[3]));

    float lsum = 0.f;
    #pragma unroll
    for (int i = 0; i < 5; i++) {
        v[i] = expf(v[i] - m);
        lsum += v[i];
    }
    #pragma unroll
    for (int o = 16; o; o >>= 1) lsum += __shfl_xor_sync(0xffffffffu, lsum, o);
    if ((tid & 31) == 0) reds[tid >> 5] = lsum;
    __syncthreads();
    float inv = 1.f / (reds[0] + reds[1] + reds[2] + reds[3]);

    #pragma unroll
    for (int i = 0; i < 5; i++) {
        int idx = tid + 128 * i;
        if (idx < LS) s[idx] = v[i] * inv;
    }
}

// ---------------------------------------------------------------------------
// Context: O[b,s,:] = p0 * v_tok[b,s,:] + P[b,s,1:] @ V_ext[b]  (K = Ee)
// ---------------------------------------------------------------------------
__global__ void __launch_bounds__(256) gemm_ctx(
    const float* __restrict__ P, const float* __restrict__ VE,
    const float* __restrict__ VT, float* __restrict__ O)
{
    const int b = blockIdx.z;
    const float* Bbase = VE + (size_t)b * Ee * Hh;

    __shared__ float As[2][16 * SSTR];
    __shared__ float Bs[2][16 * SSTR];
    const int bm = blockIdx.y * 128;
    const int bn = blockIdx.x * 128;
    WARP_IDS;
    const int ar = tid >> 2, ac = (tid & 3) << 2;
    const int br = tid >> 5, bc = (tid & 31) << 2;

    ACC_INIT;
    float pav[2][4];
    float4 pb0, pb1;

#define LOAD_C(k0)                                                            \
    do {                                                                      \
        const float* ap0 = P + (size_t)(b * Ss + bm + ar) * LS + 1 + (k0) + ac;      \
        const float* ap1 = P + (size_t)(b * Ss + bm + ar + 64) * LS + 1 + (k0) + ac; \
        pav[0][0] = ap0[0]; pav[0][1] = ap0[1];                               \
        pav[0][2] = ap0[2]; pav[0][3] = ap0[3];                               \
        pav[1][0] = ap1[0]; pav[1][1] = ap1[1];                               \
        pav[1][2] = ap1[2]; pav[1][3] = ap1[3];                               \
        pb0 = *(const float4*)(Bbase + (size_t)((k0) + br) * Hh + bn + bc);   \
        pb1 = *(const float4*)(Bbase + (size_t)((k0) + br + 8) * Hh + bn + bc); \
    } while (0)
#define STS_C(s)                                                              \
    do {                                                                      \
        As[s][(ac + 0) * SSTR + ar] = pav[0][0];                              \
        As[s][(ac + 1) * SSTR + ar] = pav[0][1];                              \
        As[s][(ac + 2) * SSTR + ar] = pav[0][2];                              \
        As[s][(ac + 3) * SSTR + ar] = pav[0][3];                              \
        As[s][(ac + 0) * SSTR + ar + 64] = pav[1][0];                         \
        As[s][(ac + 1) * SSTR + ar + 64] = pav[1][1];                         \
        As[s][(ac + 2) * SSTR + ar + 64] = pav[1][2];                         \
        As[s][(ac + 3) * SSTR + ar + 64] = pav[1][3];                         \
        *(float4*)&Bs[s][br * SSTR + bc] = pb0;                               \
        *(float4*)&Bs[s][(br + 8) * SSTR + bc] = pb1;                         \
    } while (0)

    LOAD_C(0);
    STS_C(0);
    __syncthreads();
    int buf = 0;
    for (int k0 = 0; k0 < Ee; k0 += 16) {
        const bool nxt = (k0 + 16 < Ee);
        if (nxt) LOAD_C(k0 + 16);
        FRAG_COMPUTE(As[buf], Bs[buf]);
        if (nxt) STS_C(buf ^ 1);
        __syncthreads();
        buf ^= 1;
    }
#undef LOAD_C
#undef STS_C

    #pragma unroll
    for (int mt = 0; mt < 4; mt++) {
        int r0 = b * Ss + bm + wm * 64 + mt * 16 + gid;
        int r1 = r0 + 8;
        float p0 = P[(size_t)r0 * LS];
        float p1 = P[(size_t)r1 * LS];
        #pragma unroll
        for (int nt = 0; nt < 4; nt++) {
            int col = bn + wn * 32 + nt * 8 + 2 * tg;
            float2 v0 = *(const float2*)(VT + (size_t)r0 * Hh + col);
            float2 v1 = *(const float2*)(VT + (size_t)r1 * Hh + col);
            float2 o0 = make_float2(fmaf(p0, v0.x, acc[mt][nt][0]),
                                    fmaf(p0, v0.y, acc[mt][nt][1]));
            float2 o1 = make_float2(fmaf(p1, v1.x, acc[mt][nt][2]),
                                    fmaf(p1, v1.y, acc[mt][nt][3]));
            *(float2*)(O + (size_t)r0 * Hh + col) = o0;
            *(float2*)(O + (size_t)r1 * Hh + col) = o1;
        }
    }
}

// ---------------------------------------------------------------------------
extern "C" void kernel_launch(void* const* d_in, const int* in_sizes, int n_in,
                              void* d_out, int out_size)
{
    const float* hs  = (const float*)d_in[0];
    const float* ext = (const float*)d_in[1];
    const float* Wq  = (const float*)d_in[2];
    const float* bq  = (const float*)d_in[3];
    const float* Wk  = (const float*)d_in[4];
    const float* bk  = (const float*)d_in[5];
    const float* Wv  = (const float*)d_in[6];
    const float* bv  = (const float*)d_in[7];
    float* out = (float*)d_out;

    float *q, *kt, *vt, *ke, *ve, *sc;
    cudaGetSymbolAddress((void**)&q,  g_q);
    cudaGetSymbolAddress((void**)&kt, g_kt);
    cudaGetSymbolAddress((void**)&vt, g_vt);
    cudaGetSymbolAddress((void**)&ke, g_ke);
    cudaGetSymbolAddress((void**)&ve, g_ve);
    cudaGetSymbolAddress((void**)&sc, g_sc);

    dim3 blk(256);

    // Projections (tensor-core 3xTF32)
    gemm_nn_bias<<<dim3(Hh / 128, BS / 128), blk>>>(hs,  Wq, bq, q,  BS, Hh, Hh);
    gemm_nn_bias<<<dim3(Hh / 128, BS / 128), blk>>>(hs,  Wk, bk, kt, BS, Hh, Hh);
    gemm_nn_bias<<<dim3(Hh / 128, BS / 128), blk>>>(hs,  Wv, bv, vt, BS, Hh, Hh);
    gemm_nn_bias<<<dim3(Hh / 128, BE / 128), blk>>>(ext, Wk, bk, ke, BE, Hh, Hh);
    gemm_nn_bias<<<dim3(Hh / 128, BE / 128), blk>>>(ext, Wv, bv, ve, BE, Hh, Hh);

    // Scores
    self_dot_kernel<<<BS / 8, 256>>>(q, kt, sc);
    gemm_scores_nt<<<dim3(Ee / 128, Ss / 128, Bb), blk>>>(q, ke, sc);

    // Softmax
    softmax_kernel<<<BS, 128>>>(sc);

    // Context
    gemm_ctx<<<dim3(Hh / 128, Ss / 128, Bb), blk>>>(sc, ve, vt, out);
}